// round 13
// baseline (speedup 1.0000x reference)
#include <cuda_runtime.h>
#include <cuda_bf16.h>
#include <math.h>
#include <stdint.h>

// ---------------- problem constants ----------------
#define OHW         254
#define STRIP_OROWS 8
#define STRIPS      32
#define ITERS       16          // 128 output pixels per iteration
#define NCHUNKS     21          // buildable 128-row input chunks per strip
#define RING_ROWS   896         // 7-chunk ring
#define PAD         18          // mirror pad rows (kills per-mt wrap tests)
#define PITCH       48          // bytes per A/B row (32 data + 16 pad; conflict-free)
#define OFF_RED     0           // 2 x 256 floats (ping-pong)
#define OFF_B       2048        // 9 tiles x 64 rows x 48B = 27648
#define OFF_A       29696
#define SMEM_BYTES  (OFF_A + (RING_ROWS + PAD) * PITCH)   // 73568 (x3 CTAs = 220704)

__device__ __forceinline__ uint32_t smem_u32(const void* p) {
    uint32_t a;
    asm("{ .reg .u64 t; cvta.to.shared.u64 t, %1; cvt.u32.u64 %0, t; }"
        : "=r"(a) : "l"(p));
    return a;
}
__device__ __forceinline__ void ldmatrix_x4(uint32_t& a0, uint32_t& a1,
                                            uint32_t& a2, uint32_t& a3,
                                            uint32_t addr) {
    asm volatile("ldmatrix.sync.aligned.m8n8.x4.shared.b16 {%0,%1,%2,%3}, [%4];"
                 : "=r"(a0), "=r"(a1), "=r"(a2), "=r"(a3) : "r"(addr));
}
__device__ __forceinline__ void mma_bf16(float* c, uint32_t a0, uint32_t a1,
                                         uint32_t a2, uint32_t a3,
                                         uint32_t b0, uint32_t b1) {
    asm volatile(
        "mma.sync.aligned.m16n8k16.row.col.f32.bf16.bf16.f32 "
        "{%0,%1,%2,%3}, {%4,%5,%6,%7}, {%8,%9}, {%0,%1,%2,%3};"
        : "+f"(c[0]), "+f"(c[1]), "+f"(c[2]), "+f"(c[3])
        : "r"(a0), "r"(a1), "r"(a2), "r"(a3), "r"(b0), "r"(b1));
}
__device__ __forceinline__ uint32_t pkbf(float lo, float hi) {
    __nv_bfloat162 t = __float22bfloat162_rn(make_float2(lo, hi));
    return *reinterpret_cast<uint32_t*>(&t);
}

extern __shared__ char smem[];

// Load 8 channel values (half h) for one pixel row of chunk c0.
__device__ __forceinline__ void load8(int c0, int oy0,
                                      const float* __restrict__ xb,
                                      int tid, float* v) {
    const int rr = tid & 127;
    const int h  = tid >> 7;
    const int p  = c0 * 128 + rr;
    const int iy = oy0 + (p >> 8);
    const int ix = p & 255;
    if (iy < 256) {
        const float* xp = xb + ((size_t)(h * 8) << 16) + iy * 256 + ix;
        #pragma unroll
        for (int ci = 0; ci < 8; ci++) v[ci] = __ldg(xp + (ci << 16));
    } else {
        #pragma unroll
        for (int ci = 0; ci < 8; ci++) v[ci] = 0.0f;
    }
}
// Convert + store half-row at (pre-wrapped) ring row; mirror rows < PAD.
__device__ __forceinline__ void store8_at(int ring_row, int h, const float* v) {
    uint32_t u[4];
    #pragma unroll
    for (int j = 0; j < 4; j++) u[j] = pkbf(v[2 * j], v[2 * j + 1]);
    char* base = smem + OFF_A + ring_row * PITCH + h * 16;
    *reinterpret_cast<uint4*>(base) = make_uint4(u[0], u[1], u[2], u[3]);
    if (ring_row < PAD)
        *reinterpret_cast<uint4*>(base + RING_ROWS * PITCH) =
            make_uint4(u[0], u[1], u[2], u[3]);
}

__global__ __launch_bounds__(256, 3)
void conv_mma_kernel(const float* __restrict__ x, const float* __restrict__ w,
                     const float* __restrict__ bias, float* __restrict__ out)
{
    const int tid  = threadIdx.x;
    const int warp = tid >> 5;
    const int lane = tid & 31;
    const int g    = lane >> 2;       // fragment group (row / n index)
    const int q    = lane & 3;        // thread-in-group
    const int nh   = warp & 1;        // n-half: couts [nh*32, nh*32+32)
    const int mq   = warp >> 1;       // m-quarter: rows [mq*32, mq*32+32) of 128

    const int strip = blockIdx.x;
    const int b     = blockIdx.y;
    const int oy0   = strip * STRIP_OROWS;
    const uint32_t sbase = smem_u32(smem);
    float* red = (float*)(smem + OFF_RED);

    // ---- B: 9 tiles (kh*3+kw), rows = cout n, 16 ci bf16 per row ----
    for (int idx = tid; idx < 9 * 64 * 16; idx += 256) {
        const int t  = idx >> 10;
        const int rm = idx & 1023;
        const int n  = rm >> 4;
        const int ci = rm & 15;
        const float val = __ldg(w + n * 144 + ci * 9 + t);
        *reinterpret_cast<__nv_bfloat16*>(smem + OFF_B + t * (64 * PITCH)
                                          + n * PITCH + ci * 2) = __float2bfloat16(val);
    }

    // loop-invariant bias (8 regs)
    float blo[4], bhi[4];
    #pragma unroll
    for (int nt = 0; nt < 4; nt++) {
        blo[nt] = __ldg(bias + nh * 32 + nt * 8 + 2 * q);
        bhi[nt] = __ldg(bias + nh * 32 + nt * 8 + 2 * q + 1);
    }

    const float* xb = x + ((size_t)b << 20);

    // lane-constant pieces of ldmatrix addresses
    const uint32_t a_col_off  = (uint32_t)((lane >> 4) << 4);
    const uint32_t b_lane_off = (uint32_t)((((lane >> 3) >> 1) * 8 + (lane & 7)) * PITCH
                                           + (((lane >> 3) & 1) << 4));
    const uint32_t b_base = sbase + OFF_B + (uint32_t)(nh * 32 * PITCH) + b_lane_off;
    const uint32_t a_base = sbase + OFF_A;

    // ---- prologue: chunks 0..5 (ring rows 0..767, no wrap) ----
    #pragma unroll 1
    for (int c = 0; c < 6; c++) {
        float v[8];
        load8(c, oy0, xb, tid, v);
        store8_at(c * 128 + (tid & 127), tid >> 7, v);
    }
    __syncthreads();

    // incremental ring bases, both kept in [0, RING_ROWS)
    int sts_row = 768 + (tid & 127);          // ring row of chunk 6
    int a_row0  = mq * 32 + (lane & 15);      // warp's M base for i=0

    // ---- main pipeline: ONE barrier per iteration ----
    #pragma unroll 1
    for (int i = 0; i < ITERS; i++) {
        // deferred epilogue part 2 of iteration i-1 (overlaps this MMA block)
        if (i > 0) {
            const float* redp = red + ((i - 1) & 1) * 256;
            if (tid < 128) {
                float mm = fminf(redp[2 * tid], redp[2 * tid + 1]);
                float y  = tanhf(tanhf(mm));
                const int p  = (i - 1) * 128 + tid;
                const int oy = oy0 + (p >> 8);
                const int ox = p & 255;
                if (ox < OHW && oy < OHW)
                    out[((size_t)b * OHW + oy) * OHW + ox] = y;
            }
        }

        // stage next build's 8 LDGs (chunk i+6); latency hides behind MMAs
        const int c0 = i + 6;
        float v[8];
        if (c0 < NCHUNKS) load8(c0, oy0, xb, tid, v);

        float acc[2][4][4];
        #pragma unroll
        for (int nt = 0; nt < 4; nt++)
            #pragma unroll
            for (int mt = 0; mt < 2; mt++) {
                acc[mt][nt][0] = blo[nt]; acc[mt][nt][1] = bhi[nt];
                acc[mt][nt][2] = blo[nt]; acc[mt][nt][3] = bhi[nt];
            }

        // 9 shift-steps over the ring (reads chunks i..i+5)
        #pragma unroll
        for (int kh = 0; kh < 3; kh++) {
            int rk = a_row0 + kh * 256;
            if (rk >= RING_ROWS) rk -= RING_ROWS;      // only wrap test needed
            #pragma unroll
            for (int kw = 0; kw < 3; kw++) {
                const int step = kh * 3 + kw;
                uint32_t bf[8];
                const uint32_t bt = b_base + (uint32_t)(step * 64 * PITCH);
                ldmatrix_x4(bf[0], bf[1], bf[2], bf[3], bt);
                ldmatrix_x4(bf[4], bf[5], bf[6], bf[7], bt + 16 * PITCH);
                #pragma unroll
                for (int mt = 0; mt < 2; mt++) {
                    const int row = rk + kw + mt * 16;   // < 896+18: pad covers it
                    uint32_t a0, a1, a2, a3;
                    ldmatrix_x4(a0, a1, a2, a3,
                                a_base + (uint32_t)(row * PITCH) + a_col_off);
                    #pragma unroll
                    for (int nt = 0; nt < 4; nt++)
                        mma_bf16(acc[mt][nt], a0, a1, a2, a3,
                                 bf[nt * 2], bf[nt * 2 + 1]);
                }
            }
        }

        // ---- epilogue part 1: warp min -> red[i&1] ----
        float m[4];
        #pragma unroll
        for (int mt = 0; mt < 2; mt++) {
            float lo = fminf(acc[mt][0][0], acc[mt][0][1]);
            float hi = fminf(acc[mt][0][2], acc[mt][0][3]);
            #pragma unroll
            for (int nt = 1; nt < 4; nt++) {
                lo = fminf(lo, fminf(acc[mt][nt][0], acc[mt][nt][1]));
                hi = fminf(hi, fminf(acc[mt][nt][2], acc[mt][nt][3]));
            }
            m[2 * mt]     = lo;   // row mq*32 + mt*16 + g
            m[2 * mt + 1] = hi;   // row mq*32 + mt*16 + g + 8
        }
        #pragma unroll
        for (int j = 0; j < 4; j++) {
            m[j] = fminf(m[j], __shfl_xor_sync(0xFFFFFFFFu, m[j], 1));
            m[j] = fminf(m[j], __shfl_xor_sync(0xFFFFFFFFu, m[j], 2));
        }
        float* redp = red + (i & 1) * 256;
        if (q == 0) {
            const int rb = mq * 32 + g;
            redp[(rb     ) * 2 + nh] = m[0];
            redp[(rb +  8) * 2 + nh] = m[1];
            redp[(rb + 16) * 2 + nh] = m[2];
            redp[(rb + 24) * 2 + nh] = m[3];
        }

        // commit staged build: chunk i+6 -> slot (i+6)%7 == (i-1)%7,
        // disjoint from this iteration's read slots i..i+5 (mod 7)
        if (c0 < NCHUNKS) store8_at(sts_row, tid >> 7, v);

        // single barrier: STS(i)->reads(i+1); red writes->part2; part2->rewrite
        __syncthreads();

        a_row0 += 128; if (a_row0 >= RING_ROWS) a_row0 -= RING_ROWS;
        sts_row += 128; if (sts_row >= RING_ROWS) sts_row -= RING_ROWS;
    }

    // final deferred epilogue (iteration ITERS-1)
    if (tid < 128) {
        const float* redp = red + ((ITERS - 1) & 1) * 256;
        float mm = fminf(redp[2 * tid], redp[2 * tid + 1]);
        float y  = tanhf(tanhf(mm));
        const int p  = (ITERS - 1) * 128 + tid;
        const int oy = oy0 + (p >> 8);
        const int ox = p & 255;
        if (ox < OHW && oy < OHW)
            out[((size_t)b * OHW + oy) * OHW + ox] = y;
    }
}

extern "C" void kernel_launch(void* const* d_in, const int* in_sizes, int n_in,
                              void* d_out, int out_size)
{
    const float* x    = (const float*)d_in[0];   // [64,16,256,256]
    const float* w    = (const float*)d_in[1];   // [64,16,3,3]
    const float* bias = (const float*)d_in[2];   // [64]
    float* out = (float*)d_out;                  // [64,1,254,254]

    cudaFuncSetAttribute(conv_mma_kernel,
                         cudaFuncAttributeMaxDynamicSharedMemorySize, SMEM_BYTES);

    dim3 grid(STRIPS, 64);   // 32 strips x 64 images = 2048 CTAs
    conv_mma_kernel<<<grid, 256, SMEM_BYTES>>>(x, w, bias, out);
}

// round 14
// speedup vs baseline: 1.1500x; 1.1500x over previous
#include <cuda_runtime.h>
#include <cuda_bf16.h>
#include <math.h>
#include <stdint.h>

// ---------------- problem constants ----------------
#define OHW         254
#define STRIP_OROWS 16
#define STRIPS      16
#define ITERS       16          // 256 output pixels per iteration
#define NCHUNKS     36          // buildable 128-row input chunks per strip
#define RING_ROWS   1280        // 10-chunk ring
#define PITCH       48          // bytes per A/B row (32 data + 16 pad; conflict-free)
#define OFF_RED     0           // 2 x 512 floats (ping-pong)
#define OFF_B       4096        // 9 tiles x 64 rows x 48B = 27648
#define OFF_A       (4096 + 27648)                  // 31744
#define SMEM_BYTES  (OFF_A + RING_ROWS * PITCH)     // 93184 (x2 CTAs = 186368)

__device__ __forceinline__ uint32_t smem_u32(const void* p) {
    uint32_t a;
    asm("{ .reg .u64 t; cvta.to.shared.u64 t, %1; cvt.u32.u64 %0, t; }"
        : "=r"(a) : "l"(p));
    return a;
}
__device__ __forceinline__ void ldmatrix_x4(uint32_t& a0, uint32_t& a1,
                                            uint32_t& a2, uint32_t& a3,
                                            uint32_t addr) {
    asm volatile("ldmatrix.sync.aligned.m8n8.x4.shared.b16 {%0,%1,%2,%3}, [%4];"
                 : "=r"(a0), "=r"(a1), "=r"(a2), "=r"(a3) : "r"(addr));
}
__device__ __forceinline__ void mma_bf16(float* c, uint32_t a0, uint32_t a1,
                                         uint32_t a2, uint32_t a3,
                                         uint32_t b0, uint32_t b1) {
    asm volatile(
        "mma.sync.aligned.m16n8k16.row.col.f32.bf16.bf16.f32 "
        "{%0,%1,%2,%3}, {%4,%5,%6,%7}, {%8,%9}, {%0,%1,%2,%3};"
        : "+f"(c[0]), "+f"(c[1]), "+f"(c[2]), "+f"(c[3])
        : "r"(a0), "r"(a1), "r"(a2), "r"(a3), "r"(b0), "r"(b1));
}
__device__ __forceinline__ uint32_t pkbf(float lo, float hi) {
    __nv_bfloat162 t = __float22bfloat162_rn(make_float2(lo, hi));
    return *reinterpret_cast<uint32_t*>(&t);
}

extern __shared__ char smem[];

// Load 16 channel values for one pixel row, converting to 8 packed bf16x2
// immediately (halves staging registers vs float[16]).
__device__ __forceinline__ void load16_u(int c0, int oy0,
                                         const float* __restrict__ xb,
                                         int tid, uint32_t* u) {
    const int p  = c0 * 128 + tid;
    const int iy = oy0 + (p >> 8);
    const int ix = p & 255;
    if (iy < 256) {
        const float* xp = xb + iy * 256 + ix;
        #pragma unroll
        for (int j = 0; j < 8; j++) {
            const float a = __ldg(xp + ((2 * j) << 16));
            const float c = __ldg(xp + ((2 * j + 1) << 16));
            u[j] = pkbf(a, c);
        }
    } else {
        #pragma unroll
        for (int j = 0; j < 8; j++) u[j] = 0u;
    }
}
// Store one staged pixel row at a pre-wrapped ring row.
__device__ __forceinline__ void store16_at(int ring_row, const uint32_t* u) {
    char* base = smem + OFF_A + ring_row * PITCH;
    *reinterpret_cast<uint4*>(base)      = make_uint4(u[0], u[1], u[2], u[3]);
    *reinterpret_cast<uint4*>(base + 16) = make_uint4(u[4], u[5], u[6], u[7]);
}

__global__ __launch_bounds__(256, 2)
void conv_mma_kernel(const float* __restrict__ x, const float* __restrict__ w,
                     const float* __restrict__ bias, float* __restrict__ out)
{
    const int tid  = threadIdx.x;
    const int warp = tid >> 5;
    const int lane = tid & 31;
    const int g    = lane >> 2;       // fragment group (row / n index)
    const int q    = lane & 3;        // thread-in-group
    const int nh   = warp & 1;        // n-half: couts [nh*32, nh*32+32)
    const int mq   = warp >> 1;       // m-quarter: rows [mq*64, mq*64+64) of 256

    const int strip = blockIdx.x;
    const int b     = blockIdx.y;
    const int oy0   = strip * STRIP_OROWS;
    const uint32_t sbase = smem_u32(smem);
    float* red = (float*)(smem + OFF_RED);

    // ---- B: 9 tiles (kh*3+kw), rows = cout n, 16 ci bf16 per row ----
    for (int idx = tid; idx < 9 * 64 * 16; idx += 256) {
        const int t  = idx >> 10;
        const int rm = idx & 1023;
        const int n  = rm >> 4;
        const int ci = rm & 15;
        const float val = __ldg(w + n * 144 + ci * 9 + t);
        *reinterpret_cast<__nv_bfloat16*>(smem + OFF_B + t * (64 * PITCH)
                                          + n * PITCH + ci * 2) = __float2bfloat16(val);
    }

    // loop-invariant bias (8 regs)
    float blo[4], bhi[4];
    #pragma unroll
    for (int nt = 0; nt < 4; nt++) {
        blo[nt] = __ldg(bias + nh * 32 + nt * 8 + 2 * q);
        bhi[nt] = __ldg(bias + nh * 32 + nt * 8 + 2 * q + 1);
    }

    const float* xb = x + ((size_t)b << 20);

    // lane-constant pieces of ldmatrix addresses
    const uint32_t a_col_off  = (uint32_t)((lane >> 4) << 4);
    const uint32_t b_lane_off = (uint32_t)((((lane >> 3) >> 1) * 8 + (lane & 7)) * PITCH
                                           + (((lane >> 3) & 1) << 4));
    const uint32_t b_base = sbase + OFF_B + (uint32_t)(nh * 32 * PITCH) + b_lane_off;
    const uint32_t a_base = sbase + OFF_A;

    // ---- prologue: chunks 0..7 (rows 0..1023, no wrap) ----
    #pragma unroll 1
    for (int j = 0; j < 4; j++) {
        uint32_t u[8];
        load16_u(2 * j, oy0, xb, tid, u);
        store16_at(2 * j * 128 + tid, u);
    }
    __syncthreads();

    // incremental ring bases (both already in [0, RING_ROWS))
    int sts_row = 1024 + tid;                 // ring row of chunk-8 + tid
    int a_row0  = mq * 64 + (lane & 15);      // warp's M base for i=0

    // ---- main pipeline: ONE barrier per iteration ----
    #pragma unroll 1
    for (int i = 0; i < ITERS; i++) {
        // deferred epilogue part 2 of iteration i-1 (overlaps this MMA block)
        if (i > 0) {
            const float* redp = red + ((i - 1) & 1) * 512;
            float mm = fminf(redp[2 * tid], redp[2 * tid + 1]);
            float y  = tanhf(tanhf(mm));
            const int p  = (i - 1) * 256 + tid;
            const int oy = oy0 + (p >> 8);
            const int ox = p & 255;
            if (ox < OHW && oy < OHW)
                out[((size_t)b * OHW + oy) * OHW + ox] = y;
        }

        // stage next build's LDGs (chunks 2i+8, 2i+9), convert at load
        const int c0 = 2 * i + 8;
        uint32_t u[8];
        if (c0 < NCHUNKS) load16_u(c0, oy0, xb, tid, u);

        float acc[4][4][4];
        #pragma unroll
        for (int mt = 0; mt < 4; mt++)
            #pragma unroll
            for (int nt = 0; nt < 4; nt++) {
                acc[mt][nt][0] = blo[nt]; acc[mt][nt][1] = bhi[nt];
                acc[mt][nt][2] = blo[nt]; acc[mt][nt][3] = bhi[nt];
            }

        // wrapped kh row bases
        int rks[3];
        #pragma unroll
        for (int kh = 0; kh < 3; kh++) {
            int rk = a_row0 + kh * 256;
            if (rk >= RING_ROWS) rk -= RING_ROWS;
            rks[kh] = rk;
        }

        // 9 flattened shift-steps with explicit B double-buffering
        uint32_t bf[2][8];
        ldmatrix_x4(bf[0][0], bf[0][1], bf[0][2], bf[0][3], b_base);
        ldmatrix_x4(bf[0][4], bf[0][5], bf[0][6], bf[0][7], b_base + 16 * PITCH);
        #pragma unroll
        for (int step = 0; step < 9; step++) {
            const int cur = step & 1;
            if (step < 8) {   // prefetch next step's B fragments
                const uint32_t bt = b_base + (uint32_t)((step + 1) * 64 * PITCH);
                ldmatrix_x4(bf[cur ^ 1][0], bf[cur ^ 1][1], bf[cur ^ 1][2],
                            bf[cur ^ 1][3], bt);
                ldmatrix_x4(bf[cur ^ 1][4], bf[cur ^ 1][5], bf[cur ^ 1][6],
                            bf[cur ^ 1][7], bt + 16 * PITCH);
            }
            const int kh = step / 3;
            const int kw = step - kh * 3;
            #pragma unroll
            for (int mt = 0; mt < 4; mt++) {
                int row = rks[kh] + kw + mt * 16;
                if (row >= RING_ROWS) row -= RING_ROWS;
                uint32_t a0, a1, a2, a3;
                ldmatrix_x4(a0, a1, a2, a3,
                            a_base + (uint32_t)(row * PITCH) + a_col_off);
                #pragma unroll
                for (int nt = 0; nt < 4; nt++)
                    mma_bf16(acc[mt][nt], a0, a1, a2, a3,
                             bf[cur][nt * 2], bf[cur][nt * 2 + 1]);
            }
        }

        // ---- epilogue part 1: min over this warp's 32 couts -> red[i&1] ----
        float m[8];
        #pragma unroll
        for (int mt = 0; mt < 4; mt++) {
            float lo = fminf(acc[mt][0][0], acc[mt][0][1]);
            float hi = fminf(acc[mt][0][2], acc[mt][0][3]);
            #pragma unroll
            for (int nt = 1; nt < 4; nt++) {
                lo = fminf(lo, fminf(acc[mt][nt][0], acc[mt][nt][1]));
                hi = fminf(hi, fminf(acc[mt][nt][2], acc[mt][nt][3]));
            }
            m[2 * mt]     = lo;   // row mq*64 + mt*16 + g
            m[2 * mt + 1] = hi;   // row mq*64 + mt*16 + g + 8
        }
        #pragma unroll
        for (int j = 0; j < 8; j++) {
            m[j] = fminf(m[j], __shfl_xor_sync(0xFFFFFFFFu, m[j], 1));
            m[j] = fminf(m[j], __shfl_xor_sync(0xFFFFFFFFu, m[j], 2));
        }
        float* redp = red + (i & 1) * 512;
        if (q == 0) {
            const int rb = mq * 64 + g;
            #pragma unroll
            for (int j = 0; j < 8; j++)
                redp[(rb + j * 8) * 2 + nh] = m[j];
        }

        // commit staged build — chunks 2i+8,2i+9 are disjoint from the read
        // window (2i..2i+6) in the 10-chunk ring: no extra barrier needed
        if (c0 < NCHUNKS) store16_at(sts_row, u);

        // single barrier: STS(i)->reads(i+1); red writes->part2; part2->rewrite
        __syncthreads();

        a_row0 += 256; if (a_row0 >= RING_ROWS) a_row0 -= RING_ROWS;
        sts_row += 256; if (sts_row >= RING_ROWS) sts_row -= RING_ROWS;
    }

    // final deferred epilogue (iteration ITERS-1)
    {
        const float* redp = red + ((ITERS - 1) & 1) * 512;
        float mm = fminf(redp[2 * tid], redp[2 * tid + 1]);
        float y  = tanhf(tanhf(mm));
        const int p  = (ITERS - 1) * 256 + tid;
        const int oy = oy0 + (p >> 8);
        const int ox = p & 255;
        if (ox < OHW && oy < OHW)
            out[((size_t)b * OHW + oy) * OHW + ox] = y;
    }
}

extern "C" void kernel_launch(void* const* d_in, const int* in_sizes, int n_in,
                              void* d_out, int out_size)
{
    const float* x    = (const float*)d_in[0];   // [64,16,256,256]
    const float* w    = (const float*)d_in[1];   // [64,16,3,3]
    const float* bias = (const float*)d_in[2];   // [64]
    float* out = (float*)d_out;                  // [64,1,254,254]

    cudaFuncSetAttribute(conv_mma_kernel,
                         cudaFuncAttributeMaxDynamicSharedMemorySize, SMEM_BYTES);

    dim3 grid(STRIPS, 64);   // 16 strips x 64 images = 1024 CTAs
    conv_mma_kernel<<<grid, 256, SMEM_BYTES>>>(x, w, bias, out);
}